// round 16
// baseline (speedup 1.0000x reference)
#include <cuda_runtime.h>
#include <cuda_fp16.h>
#include <math.h>
#include <stdint.h>

#define T_TOK 2048
#define H_DIM 1024
#define N1_DIM 2048
#define E_EXP 8
#define NROWS_MAX 4096
#define KSTAGE 32        // halfs of K per stage
#define NT_STAGES 32     // 1024 / 32
#define PIPE 4

// ---------------- device scratch (no allocations allowed) ----------------
struct Ctrl { int counts[E_EXP]; int fill[E_EXP]; int bflag; };
__device__ Ctrl   g_ctrl;                   // zeroed per replay via cudaMemsetAsync
__device__ int    g_offsets[E_EXP + 1];
__device__ int    g_topk_id[NROWS_MAX];
__device__ float  g_topk_w[NROWS_MAX];
__device__ int    g_rows_token[NROWS_MAX];
__device__ float  g_rows_weight[NROWS_MAX];
__device__ __half g_xrh[(size_t)T_TOK * 1024];              // 4 MB  fp16 x
__device__ __half g_acth[(size_t)NROWS_MAX * 1024];         // 8 MB  fp16 act
__device__ __half g_w1h[(size_t)E_EXP * H_DIM * N1_DIM];    // 32 MB fp16 w1
__device__ __half g_w2h[(size_t)E_EXP * H_DIM * H_DIM];     // 16 MB fp16 w2

// ---------------- helpers ----------------
__device__ __forceinline__ uint32_t s2u(const void* p) {
    uint32_t a;
    asm("{ .reg .u64 t; cvta.to.shared.u64 t, %1; cvt.u32.u64 %0, t; }" : "=r"(a) : "l"(p));
    return a;
}
__device__ __forceinline__ void cpa16(uint32_t s, const void* g) {
    asm volatile("cp.async.cg.shared.global [%0], [%1], 16;" :: "r"(s), "l"(g));
}
__device__ __forceinline__ void redg(float* p, float v) {
    asm volatile("red.global.add.f32 [%0], %1;" :: "l"(p), "f"(v) : "memory");
}
__device__ __forceinline__ void mma_f16(float* c, const uint32_t* a, const uint32_t* b) {
    asm volatile(
        "mma.sync.aligned.m16n8k16.row.col.f32.f16.f16.f32 "
        "{%0,%1,%2,%3}, {%4,%5,%6,%7}, {%8,%9}, {%0,%1,%2,%3};"
        : "+f"(c[0]), "+f"(c[1]), "+f"(c[2]), "+f"(c[3])
        : "r"(a[0]), "r"(a[1]), "r"(a[2]), "r"(a[3]), "r"(b[0]), "r"(b[1]));
}
#define LDSM_X4(r, a)                                                         \
    asm volatile("ldmatrix.sync.aligned.m8n8.x4.shared.b16 {%0,%1,%2,%3},[%4];" \
        : "=r"((r)[0]), "=r"((r)[1]), "=r"((r)[2]), "=r"((r)[3]) : "r"(a))
#define LDSM_X4T(r, a)                                                        \
    asm volatile("ldmatrix.sync.aligned.m8n8.x4.trans.shared.b16 {%0,%1,%2,%3},[%4];" \
        : "=r"((r)[0]), "=r"((r)[1]), "=r"((r)[2]), "=r"((r)[3]) : "r"(a))

// ---------------- kernel 0: fused w1-convert + router ----------------
#define W1_N4 (E_EXP * H_DIM * N1_DIM / 4)   // 4M float4
#define W2_N4 (E_EXP * H_DIM * H_DIM / 4)    // 2M float4
#define RTR_BLK 256
#define CVT_BLK 2048

__global__ void cvt_router_kernel(const float4* __restrict__ w1,
                                  const float* __restrict__ x,
                                  const float* __restrict__ rw,
                                  const float* __restrict__ rb,
                                  float* __restrict__ ew_out) {
    if (blockIdx.x >= RTR_BLK) {
        __half2* d1 = (__half2*)g_w1h;
        int stride = CVT_BLK * blockDim.x;
        for (int i = (blockIdx.x - RTR_BLK) * blockDim.x + threadIdx.x;
             i < W1_N4; i += stride) {
            float4 v = w1[i];
            d1[2 * i + 0] = __floats2half2_rn(v.x, v.y);
            d1[2 * i + 1] = __floats2half2_rn(v.z, v.w);
        }
        return;
    }
    int gwarp = (blockIdx.x * blockDim.x + threadIdx.x) >> 5;
    int lane  = threadIdx.x & 31;

    const float* xr = x + (size_t)gwarp * H_DIM;
    float xv[32];
#pragma unroll
    for (int j = 0; j < 32; j++) xv[j] = xr[j * 32 + lane];

    __half* xo = g_xrh + (size_t)gwarp * H_DIM;
#pragma unroll
    for (int j = 0; j < 32; j++) xo[j * 32 + lane] = __float2half_rn(xv[j]);

    float p[E_EXP];
#pragma unroll
    for (int e = 0; e < E_EXP; e++) {
        const float* w = rw + e * H_DIM;
        float s = 0.f;
#pragma unroll
        for (int j = 0; j < 32; j++) s += xv[j] * w[j * 32 + lane];
#pragma unroll
        for (int o = 16; o > 0; o >>= 1) s += __shfl_xor_sync(0xffffffffu, s, o);
        p[e] = s + rb[e];
    }
    float m = p[0];
#pragma unroll
    for (int e = 1; e < E_EXP; e++) m = fmaxf(m, p[e]);
    float sum = 0.f;
#pragma unroll
    for (int e = 0; e < E_EXP; e++) { p[e] = expf(p[e] - m); sum += p[e]; }
    float inv = 1.f / sum;
#pragma unroll
    for (int e = 0; e < E_EXP; e++) p[e] *= inv;

    int i0 = 0;
#pragma unroll
    for (int e = 1; e < E_EXP; e++) if (p[e] > p[i0]) i0 = e;
    int i1 = (i0 == 0) ? 1 : 0;
#pragma unroll
    for (int e = 0; e < E_EXP; e++) if (e != i0 && p[e] > p[i1]) i1 = e;

    if (lane == 0) {
        g_topk_id[gwarp * 2 + 0] = i0;
        g_topk_id[gwarp * 2 + 1] = i1;
        g_topk_w[gwarp * 2 + 0] = p[i0];
        g_topk_w[gwarp * 2 + 1] = p[i1];
        atomicAdd(&g_ctrl.counts[i0], 1);
        atomicAdd(&g_ctrl.counts[i1], 1);
        if (ew_out) {
            ew_out[gwarp * 2 + 0] = p[i0];
            ew_out[gwarp * 2 + 1] = p[i1];
        }
    }
}

// ---------------- kernel 1: w2-convert + offsets + row-list scatter ------
// 592 blocks (all co-resident; capacity 1184): phase 1 converts w2 f32->f16
// grid-stride; phase 2: global thread 0 computes prefix sums, threads < 4096
// spin then scatter. w2h complete at kernel exit (boundary before GEMM2).
#define BUILD_BLK 592
__global__ void build_kernel(const float4* __restrict__ w2) {
    __half2* d2 = (__half2*)g_w2h;
    const int gstride = BUILD_BLK * 256;
    for (int i = blockIdx.x * 256 + threadIdx.x; i < W2_N4; i += gstride) {
        float4 v = w2[i];
        d2[2 * i + 0] = __floats2half2_rn(v.x, v.y);
        d2[2 * i + 1] = __floats2half2_rn(v.z, v.w);
    }
    int i = blockIdx.x * 256 + threadIdx.x;
    if (i == 0) {
        int s = 0;
        for (int e = 0; e < E_EXP; e++) { g_offsets[e] = s; s += g_ctrl.counts[e]; }
        g_offsets[E_EXP] = s;
        __threadfence();
        *(volatile int*)&g_ctrl.bflag = 1;
    }
    if (i >= NROWS_MAX) return;
    if (i != 0) {
        while (*(volatile int*)&g_ctrl.bflag == 0) { }
        __threadfence();
    }
    int e = g_topk_id[i];
    int pos = g_offsets[e] + atomicAdd(&g_ctrl.fill[e], 1);
    g_rows_token[pos]  = i >> 1;
    g_rows_weight[pos] = g_topk_w[i];
}

// ---------------- fp16 mma.sync grouped GEMM, cp.async 4-stage ----------
#define AS_STRIDE 40
#define BS_STRIDE 136
#define A_STG_BYTES (128 * AS_STRIDE * 2)   // 10240
#define B_STG_BYTES (32 * BS_STRIDE * 2)    // 8704
#define STAGE_BYTES (A_STG_BYTES + B_STG_BYTES)  // 18944
#define ROW_OFF (PIPE * STAGE_BYTES)        // 75776
#define DYN_SMEM (ROW_OFF + 512)            // 76288

template<int N_DIM, bool IS_G1>
__global__ __launch_bounds__(256, 2)
void moe_gemm_mma(const float* __restrict__ Wb, float* __restrict__ Out) {
    const int e = blockIdx.z;
    const int rowStart = g_offsets[e] + blockIdx.y * 128;
    const int rowEnd   = g_offsets[e + 1];
    if (rowStart >= rowEnd) return;
    const int n0  = blockIdx.x * 128;
    const int tid = threadIdx.x;
    const int wid = tid >> 5, lane = tid & 31;

    extern __shared__ char smc[];
    int* sRow = (int*)(smc + ROW_OFF);
    const uint32_t smem_u = s2u(smc);

    if (tid < 128) {
        int gr = rowStart + tid;
        if (gr >= rowEnd) gr = rowEnd - 1;
        sRow[tid] = IS_G1 ? g_rows_token[gr] : gr;
    }
    __syncthreads();

    const __half* Ah = IS_G1 ? (const __half*)g_xrh : (const __half*)g_acth;
    const __half* Wh = (IS_G1 ? (const __half*)g_w1h : (const __half*)g_w2h)
                       + (size_t)e * H_DIM * N_DIM + n0;

    const __half* aP = Ah + (size_t)sRow[tid >> 1] * H_DIM + (tid & 1) * 16;
    const int bK = tid >> 3;
    const int bC = (tid & 7) * 2;
    const uint32_t sa = smem_u + ((tid >> 1) * AS_STRIDE + (tid & 1) * 16) * 2;
    const uint32_t sb = smem_u + A_STG_BYTES + (bK * BS_STRIDE + bC * 8) * 2;

#define ISSUE(KT) do {                                                             \
    if ((KT) < NT_STAGES) {                                                        \
        int _k0 = (KT) * KSTAGE;                                                   \
        uint32_t _so = ((KT) % PIPE) * STAGE_BYTES;                                \
        _Pragma("unroll")                                                          \
        for (int t = 0; t < 2; t++) {                                              \
            cpa16(sa + _so + t * 16, aP + _k0 + t * 8);                            \
            cpa16(sb + _so + t * 16,                                               \
                  Wh + (size_t)(_k0 + bK) * N_DIM + (bC + t) * 8);                 \
        }                                                                          \
    }                                                                              \
    asm volatile("cp.async.commit_group;" ::: "memory");                           \
} while (0)

    ISSUE(0); ISSUE(1); ISSUE(2);

    const int wm0 = (wid >> 2) * 64;
    const int wn0 = (wid & 3) * 32;
    const int g   = lane >> 2;
    const int tg  = lane & 3;

    const int a_rl   = lane & 15;
    const int a_koff = (lane >> 4) * 8;
    const int b_k    = (lane & 7) + ((lane >> 3) & 1) * 8;
    const int b_n    = (lane >> 4) * 8;
    const uint32_t aBase = smem_u + ((wm0 + a_rl) * AS_STRIDE + a_koff) * 2;
    const uint32_t bBase = smem_u + A_STG_BYTES + (b_k * BS_STRIDE + wn0 + b_n) * 2;

    float acc[4][4][4];
#pragma unroll
    for (int m = 0; m < 4; m++)
#pragma unroll
        for (int n = 0; n < 4; n++)
#pragma unroll
            for (int q = 0; q < 4; q++) acc[m][n][q] = 0.f;

    int buf = 0;
    for (int kt = 0; kt < NT_STAGES; kt++) {
        asm volatile("cp.async.wait_group 2;" ::: "memory");
        __syncthreads();
        ISSUE(kt + 3);   // overwrites slot (kt-1)%4 — consumed pre-barrier

        const uint32_t so = buf * STAGE_BYTES;
#pragma unroll
        for (int kk = 0; kk < 2; kk++) {            // two K=16 steps
            uint32_t af[4][4], bf[2][4];
#pragma unroll
            for (int m = 0; m < 4; m++)
                LDSM_X4(af[m], aBase + so + m * (16 * AS_STRIDE * 2) + kk * 32);
#pragma unroll
            for (int p = 0; p < 2; p++)
                LDSM_X4T(bf[p], bBase + so + p * 32 + kk * (16 * BS_STRIDE * 2));
#pragma unroll
            for (int m = 0; m < 4; m++)
#pragma unroll
                for (int n = 0; n < 4; n++)
                    mma_f16(acc[m][n], af[m], &bf[n >> 1][(n & 1) * 2]);
        }
        buf = (buf == PIPE - 1) ? 0 : buf + 1;
    }
#undef ISSUE

    // ---------------- epilogue ----------------
    const float* bias = Wb + (size_t)e * N_DIM + n0;
#pragma unroll
    for (int m = 0; m < 4; m++) {
#pragma unroll
        for (int half = 0; half < 2; half++) {
            int gr = rowStart + wm0 + m * 16 + g + half * 8;
            if (gr < rowEnd) {
                if (IS_G1) {
                    __half* dst = g_acth + (size_t)gr * 1024 + (n0 >> 1);
#pragma unroll
                    for (int n = 0; n < 4; n++) {
                        int c = wn0 + n * 8 + tg * 2;
                        float gate = acc[m][n][half * 2 + 0] + bias[c];
                        float up   = acc[m][n][half * 2 + 1] + bias[c + 1];
                        gate = fminf(gate, 7.0f);
                        up   = fminf(fmaxf(up, -7.0f), 7.0f);
                        float glu = gate / (1.0f + expf(-1.702f * gate));
                        dst[c >> 1] = __float2half_rn((up + 1.0f) * glu);
                    }
                } else {
                    // 2 atomic addends per element, fp32 add commutative
                    int   token = g_rows_token[gr];
                    float wgt   = g_rows_weight[gr];
                    float* dst  = Out + (size_t)token * 1024 + n0;
#pragma unroll
                    for (int n = 0; n < 4; n++) {
                        int c = wn0 + n * 8 + tg * 2;
                        redg(&dst[c],     wgt * (acc[m][n][half * 2 + 0] + bias[c]));
                        redg(&dst[c + 1], wgt * (acc[m][n][half * 2 + 1] + bias[c + 1]));
                    }
                }
            }
        }
    }
}

// ---------------- launch ----------------
extern "C" void kernel_launch(void* const* d_in, const int* in_sizes, int n_in,
                              void* d_out, int out_size) {
    const float* x   = (const float*)d_in[0];
    const float* rw  = (const float*)d_in[1];
    const float* rb  = (const float*)d_in[2];
    const float* w1  = (const float*)d_in[3];
    const float* w1b = (const float*)d_in[4];
    const float* w2  = (const float*)d_in[5];
    const float* w2b = (const float*)d_in[6];
    float* out = (float*)d_out;
    (void)in_sizes; (void)n_in;

    cudaFuncSetAttribute(moe_gemm_mma<N1_DIM, true>,
                         cudaFuncAttributeMaxDynamicSharedMemorySize, DYN_SMEM);
    cudaFuncSetAttribute(moe_gemm_mma<H_DIM, false>,
                         cudaFuncAttributeMaxDynamicSharedMemorySize, DYN_SMEM);

    void* ctrl_addr = nullptr;
    cudaGetSymbolAddress(&ctrl_addr, g_ctrl);

    float* ew = (out_size >= T_TOK * H_DIM + T_TOK * 2) ? (out + T_TOK * H_DIM)
                                                        : nullptr;
    cudaMemsetAsync(ctrl_addr, 0, sizeof(Ctrl));
    cudaMemsetAsync(out, 0, (size_t)T_TOK * H_DIM * sizeof(float));
    cvt_router_kernel<<<RTR_BLK + CVT_BLK, 256>>>(
        (const float4*)w1, x, rw, rb, ew);
    build_kernel<<<BUILD_BLK, 256>>>((const float4*)w2);
    // grid.y = 32: empty CTAs are nearly free, and the larger bid space
    // spreads active tiles across SMs (y=16 clumped them; GEMM2 47->54us)
    moe_gemm_mma<N1_DIM, true><<<dim3(N1_DIM / 128, 32, E_EXP), 256, DYN_SMEM>>>(w1b, nullptr);
    moe_gemm_mma<H_DIM, false><<<dim3(H_DIM / 128, 32, E_EXP), 256, DYN_SMEM>>>(w2b, out);
}

// round 17
// speedup vs baseline: 1.0487x; 1.0487x over previous
#include <cuda_runtime.h>
#include <cuda_fp16.h>
#include <math.h>
#include <stdint.h>

#define T_TOK 2048
#define H_DIM 1024
#define N1_DIM 2048
#define E_EXP 8
#define NROWS_MAX 4096
#define KSTAGE 32        // halfs of K per stage
#define NT_STAGES 32     // 1024 / 32
#define PIPE 4

// ---------------- device scratch (no allocations allowed) ----------------
struct Ctrl { int counts[E_EXP]; int fill[E_EXP]; int bflag; };
__device__ Ctrl   g_ctrl;                   // zeroed per replay via cudaMemsetAsync
__device__ int    g_offsets[E_EXP + 1];
__device__ int    g_topk_id[NROWS_MAX];
__device__ float  g_topk_w[NROWS_MAX];
__device__ int    g_rows_token[NROWS_MAX];
__device__ float  g_rows_weight[NROWS_MAX];
__device__ __half g_xrh[(size_t)T_TOK * 1024];              // 4 MB  fp16 x
__device__ __half g_acth[(size_t)NROWS_MAX * 1024];         // 8 MB  fp16 act
__device__ __half g_w1h[(size_t)E_EXP * H_DIM * N1_DIM];    // 32 MB fp16 w1
__device__ __half g_w2h[(size_t)E_EXP * H_DIM * H_DIM];     // 16 MB fp16 w2

// ---------------- helpers ----------------
__device__ __forceinline__ uint32_t s2u(const void* p) {
    uint32_t a;
    asm("{ .reg .u64 t; cvta.to.shared.u64 t, %1; cvt.u32.u64 %0, t; }" : "=r"(a) : "l"(p));
    return a;
}
__device__ __forceinline__ void cpa16(uint32_t s, const void* g) {
    asm volatile("cp.async.cg.shared.global [%0], [%1], 16;" :: "r"(s), "l"(g));
}
__device__ __forceinline__ void redg(float* p, float v) {
    asm volatile("red.global.add.f32 [%0], %1;" :: "l"(p), "f"(v) : "memory");
}
__device__ __forceinline__ void mma_f16(float* c, const uint32_t* a, const uint32_t* b) {
    asm volatile(
        "mma.sync.aligned.m16n8k16.row.col.f32.f16.f16.f32 "
        "{%0,%1,%2,%3}, {%4,%5,%6,%7}, {%8,%9}, {%0,%1,%2,%3};"
        : "+f"(c[0]), "+f"(c[1]), "+f"(c[2]), "+f"(c[3])
        : "r"(a[0]), "r"(a[1]), "r"(a[2]), "r"(a[3]), "r"(b[0]), "r"(b[1]));
}
#define LDSM_X4(r, a)                                                         \
    asm volatile("ldmatrix.sync.aligned.m8n8.x4.shared.b16 {%0,%1,%2,%3},[%4];" \
        : "=r"((r)[0]), "=r"((r)[1]), "=r"((r)[2]), "=r"((r)[3]) : "r"(a))
#define LDSM_X4T(r, a)                                                        \
    asm volatile("ldmatrix.sync.aligned.m8n8.x4.trans.shared.b16 {%0,%1,%2,%3},[%4];" \
        : "=r"((r)[0]), "=r"((r)[1]), "=r"((r)[2]), "=r"((r)[3]) : "r"(a))

// ---------------- kernel 0: fused w1-convert + router ----------------
#define W1_N4 (E_EXP * H_DIM * N1_DIM / 4)   // 4M float4
#define W2_N4 (E_EXP * H_DIM * H_DIM / 4)    // 2M float4
#define RTR_BLK 256
#define CVT_BLK 2048

__global__ void cvt_router_kernel(const float4* __restrict__ w1,
                                  const float* __restrict__ x,
                                  const float* __restrict__ rw,
                                  const float* __restrict__ rb,
                                  float* __restrict__ ew_out) {
    if (blockIdx.x >= RTR_BLK) {
        __half2* d1 = (__half2*)g_w1h;
        int stride = CVT_BLK * blockDim.x;
        for (int i = (blockIdx.x - RTR_BLK) * blockDim.x + threadIdx.x;
             i < W1_N4; i += stride) {
            float4 v = w1[i];
            d1[2 * i + 0] = __floats2half2_rn(v.x, v.y);
            d1[2 * i + 1] = __floats2half2_rn(v.z, v.w);
        }
        return;
    }
    int gwarp = (blockIdx.x * blockDim.x + threadIdx.x) >> 5;
    int lane  = threadIdx.x & 31;

    const float* xr = x + (size_t)gwarp * H_DIM;
    float xv[32];
#pragma unroll
    for (int j = 0; j < 32; j++) xv[j] = xr[j * 32 + lane];

    __half* xo = g_xrh + (size_t)gwarp * H_DIM;
#pragma unroll
    for (int j = 0; j < 32; j++) xo[j * 32 + lane] = __float2half_rn(xv[j]);

    float p[E_EXP];
#pragma unroll
    for (int e = 0; e < E_EXP; e++) {
        const float* w = rw + e * H_DIM;
        float s = 0.f;
#pragma unroll
        for (int j = 0; j < 32; j++) s += xv[j] * w[j * 32 + lane];
#pragma unroll
        for (int o = 16; o > 0; o >>= 1) s += __shfl_xor_sync(0xffffffffu, s, o);
        p[e] = s + rb[e];
    }
    float m = p[0];
#pragma unroll
    for (int e = 1; e < E_EXP; e++) m = fmaxf(m, p[e]);
    float sum = 0.f;
#pragma unroll
    for (int e = 0; e < E_EXP; e++) { p[e] = expf(p[e] - m); sum += p[e]; }
    float inv = 1.f / sum;
#pragma unroll
    for (int e = 0; e < E_EXP; e++) p[e] *= inv;

    int i0 = 0;
#pragma unroll
    for (int e = 1; e < E_EXP; e++) if (p[e] > p[i0]) i0 = e;
    int i1 = (i0 == 0) ? 1 : 0;
#pragma unroll
    for (int e = 0; e < E_EXP; e++) if (e != i0 && p[e] > p[i1]) i1 = e;

    if (lane == 0) {
        g_topk_id[gwarp * 2 + 0] = i0;
        g_topk_id[gwarp * 2 + 1] = i1;
        g_topk_w[gwarp * 2 + 0] = p[i0];
        g_topk_w[gwarp * 2 + 1] = p[i1];
        atomicAdd(&g_ctrl.counts[i0], 1);
        atomicAdd(&g_ctrl.counts[i1], 1);
        if (ew_out) {
            ew_out[gwarp * 2 + 0] = p[i0];
            ew_out[gwarp * 2 + 1] = p[i1];
        }
    }
}

// ---------------- kernel 1: w2-convert + offsets + row-list scatter ------
#define BUILD_BLK 592
__global__ void build_kernel(const float4* __restrict__ w2) {
    __half2* d2 = (__half2*)g_w2h;
    const int gstride = BUILD_BLK * 256;
    for (int i = blockIdx.x * 256 + threadIdx.x; i < W2_N4; i += gstride) {
        float4 v = w2[i];
        d2[2 * i + 0] = __floats2half2_rn(v.x, v.y);
        d2[2 * i + 1] = __floats2half2_rn(v.z, v.w);
    }
    int i = blockIdx.x * 256 + threadIdx.x;
    if (i == 0) {
        int s = 0;
        for (int e = 0; e < E_EXP; e++) { g_offsets[e] = s; s += g_ctrl.counts[e]; }
        g_offsets[E_EXP] = s;
        __threadfence();
        *(volatile int*)&g_ctrl.bflag = 1;
    }
    if (i >= NROWS_MAX) return;
    if (i != 0) {
        while (*(volatile int*)&g_ctrl.bflag == 0) { }
        __threadfence();
    }
    int e = g_topk_id[i];
    int pos = g_offsets[e] + atomicAdd(&g_ctrl.fill[e], 1);
    g_rows_token[pos]  = i >> 1;
    g_rows_weight[pos] = g_topk_w[i];
}

// ---------------- fp16 mma.sync grouped GEMM, cp.async 4-stage ----------
// NSPLIT: K-split factor (GEMM2 only; GEMM1 epilogue is nonlinear).
#define AS_STRIDE 40
#define BS_STRIDE 136
#define A_STG_BYTES (128 * AS_STRIDE * 2)   // 10240
#define B_STG_BYTES (32 * BS_STRIDE * 2)    // 8704
#define STAGE_BYTES (A_STG_BYTES + B_STG_BYTES)  // 18944
#define ROW_OFF (PIPE * STAGE_BYTES)        // 75776
#define DYN_SMEM (ROW_OFF + 512)            // 76288

template<int N_DIM, bool IS_G1, int NSPLIT>
__global__ __launch_bounds__(256, 2)
void moe_gemm_mma(const float* __restrict__ Wb, float* __restrict__ Out) {
    const int e    = blockIdx.z;
    const int ks   = (NSPLIT > 1) ? (blockIdx.y % NSPLIT) : 0;
    const int yblk = (NSPLIT > 1) ? (blockIdx.y / NSPLIT) : blockIdx.y;
    const int rowStart = g_offsets[e] + yblk * 128;
    const int rowEnd   = g_offsets[e + 1];
    if (rowStart >= rowEnd) return;
    const int n0  = blockIdx.x * 128;
    const int tid = threadIdx.x;
    const int wid = tid >> 5, lane = tid & 31;
    const int kbase = ks * (1024 / NSPLIT);         // halfs of K
    constexpr int NT_LOCAL = NT_STAGES / NSPLIT;

    extern __shared__ char smc[];
    int* sRow = (int*)(smc + ROW_OFF);
    const uint32_t smem_u = s2u(smc);

    if (tid < 128) {
        int gr = rowStart + tid;
        if (gr >= rowEnd) gr = rowEnd - 1;
        sRow[tid] = IS_G1 ? g_rows_token[gr] : gr;
    }
    __syncthreads();

    const __half* Ah = IS_G1 ? (const __half*)g_xrh : (const __half*)g_acth;
    const __half* Wh = (IS_G1 ? (const __half*)g_w1h : (const __half*)g_w2h)
                       + (size_t)e * H_DIM * N_DIM + (size_t)kbase * N_DIM + n0;

    const __half* aP = Ah + (size_t)sRow[tid >> 1] * H_DIM + kbase + (tid & 1) * 16;
    const int bK = tid >> 3;
    const int bC = (tid & 7) * 2;
    const uint32_t sa = smem_u + ((tid >> 1) * AS_STRIDE + (tid & 1) * 16) * 2;
    const uint32_t sb = smem_u + A_STG_BYTES + (bK * BS_STRIDE + bC * 8) * 2;

#define ISSUE(KT) do {                                                             \
    if ((KT) < NT_LOCAL) {                                                         \
        int _k0 = (KT) * KSTAGE;                                                   \
        uint32_t _so = ((KT) % PIPE) * STAGE_BYTES;                                \
        _Pragma("unroll")                                                          \
        for (int t = 0; t < 2; t++) {                                              \
            cpa16(sa + _so + t * 16, aP + _k0 + t * 8);                            \
            cpa16(sb + _so + t * 16,                                               \
                  Wh + (size_t)(_k0 + bK) * N_DIM + (bC + t) * 8);                 \
        }                                                                          \
    }                                                                              \
    asm volatile("cp.async.commit_group;" ::: "memory");                           \
} while (0)

    ISSUE(0); ISSUE(1); ISSUE(2);

    const int wm0 = (wid >> 2) * 64;
    const int wn0 = (wid & 3) * 32;
    const int g   = lane >> 2;
    const int tg  = lane & 3;

    const int a_rl   = lane & 15;
    const int a_koff = (lane >> 4) * 8;
    const int b_k    = (lane & 7) + ((lane >> 3) & 1) * 8;
    const int b_n    = (lane >> 4) * 8;
    const uint32_t aBase = smem_u + ((wm0 + a_rl) * AS_STRIDE + a_koff) * 2;
    const uint32_t bBase = smem_u + A_STG_BYTES + (b_k * BS_STRIDE + wn0 + b_n) * 2;

    float acc[4][4][4];
#pragma unroll
    for (int m = 0; m < 4; m++)
#pragma unroll
        for (int n = 0; n < 4; n++)
#pragma unroll
            for (int q = 0; q < 4; q++) acc[m][n][q] = 0.f;

    int buf = 0;
    for (int kt = 0; kt < NT_LOCAL; kt++) {
        asm volatile("cp.async.wait_group 2;" ::: "memory");
        __syncthreads();
        ISSUE(kt + 3);   // overwrites slot (kt-1)%4 — consumed pre-barrier

        const uint32_t so = buf * STAGE_BYTES;
#pragma unroll
        for (int kk = 0; kk < 2; kk++) {            // two K=16 steps
            uint32_t af[4][4], bf[2][4];
#pragma unroll
            for (int m = 0; m < 4; m++)
                LDSM_X4(af[m], aBase + so + m * (16 * AS_STRIDE * 2) + kk * 32);
#pragma unroll
            for (int p = 0; p < 2; p++)
                LDSM_X4T(bf[p], bBase + so + p * 32 + kk * (16 * BS_STRIDE * 2));
#pragma unroll
            for (int m = 0; m < 4; m++)
#pragma unroll
                for (int n = 0; n < 4; n++)
                    mma_f16(acc[m][n], af[m], &bf[n >> 1][(n & 1) * 2]);
        }
        buf = (buf == PIPE - 1) ? 0 : buf + 1;
    }
#undef ISSUE

    // ---------------- epilogue ----------------
    const float* bias = Wb + (size_t)e * N_DIM + n0;
    const float bmul = (ks == 0) ? 1.f : 0.f;   // bias only from K-split 0
#pragma unroll
    for (int m = 0; m < 4; m++) {
#pragma unroll
        for (int half = 0; half < 2; half++) {
            int gr = rowStart + wm0 + m * 16 + g + half * 8;
            if (gr < rowEnd) {
                if (IS_G1) {
                    __half* dst = g_acth + (size_t)gr * 1024 + (n0 >> 1);
#pragma unroll
                    for (int n = 0; n < 4; n++) {
                        int c = wn0 + n * 8 + tg * 2;
                        float gate = acc[m][n][half * 2 + 0] + bias[c];
                        float up   = acc[m][n][half * 2 + 1] + bias[c + 1];
                        gate = fminf(gate, 7.0f);
                        up   = fminf(fmaxf(up, -7.0f), 7.0f);
                        float glu = gate / (1.0f + expf(-1.702f * gate));
                        dst[c >> 1] = __float2half_rn((up + 1.0f) * glu);
                    }
                } else {
                    int   token = g_rows_token[gr];
                    float wgt   = g_rows_weight[gr];
                    float* dst  = Out + (size_t)token * 1024 + n0;
#pragma unroll
                    for (int n = 0; n < 4; n++) {
                        int c = wn0 + n * 8 + tg * 2;
                        redg(&dst[c],     wgt * (acc[m][n][half * 2 + 0] + bmul * bias[c]));
                        redg(&dst[c + 1], wgt * (acc[m][n][half * 2 + 1] + bmul * bias[c + 1]));
                    }
                }
            }
        }
    }
}

// ---------------- launch ----------------
extern "C" void kernel_launch(void* const* d_in, const int* in_sizes, int n_in,
                              void* d_out, int out_size) {
    const float* x   = (const float*)d_in[0];
    const float* rw  = (const float*)d_in[1];
    const float* rb  = (const float*)d_in[2];
    const float* w1  = (const float*)d_in[3];
    const float* w1b = (const float*)d_in[4];
    const float* w2  = (const float*)d_in[5];
    const float* w2b = (const float*)d_in[6];
    float* out = (float*)d_out;
    (void)in_sizes; (void)n_in;

    cudaFuncSetAttribute(moe_gemm_mma<N1_DIM, true, 1>,
                         cudaFuncAttributeMaxDynamicSharedMemorySize, DYN_SMEM);
    cudaFuncSetAttribute(moe_gemm_mma<H_DIM, false, 2>,
                         cudaFuncAttributeMaxDynamicSharedMemorySize, DYN_SMEM);

    void* ctrl_addr = nullptr;
    cudaGetSymbolAddress(&ctrl_addr, g_ctrl);

    float* ew = (out_size >= T_TOK * H_DIM + T_TOK * 2) ? (out + T_TOK * H_DIM)
                                                        : nullptr;
    cudaMemsetAsync(ctrl_addr, 0, sizeof(Ctrl));
    cudaMemsetAsync(out, 0, (size_t)T_TOK * H_DIM * sizeof(float));
    cvt_router_kernel<<<RTR_BLK + CVT_BLK, 256>>>(
        (const float4*)w1, x, rw, rb, ew);
    build_kernel<<<BUILD_BLK, 256>>>((const float4*)w2);
    // GEMM1: unsplit (nonlinear epilogue), y=16 as in R15 best
    moe_gemm_mma<N1_DIM, true, 1><<<dim3(N1_DIM / 128, 16, E_EXP), 256, DYN_SMEM>>>(w1b, nullptr);
    // GEMM2: K-split x2 -> ~540 active CTAs (was ~270, 0.9 waves)
    moe_gemm_mma<H_DIM, false, 2><<<dim3(H_DIM / 128, 32, E_EXP), 256, DYN_SMEM>>>(w2b, out);
}